// round 1
// baseline (speedup 1.0000x reference)
#include <cuda_runtime.h>
#include <cstdint>

// Problem constants (fixed by the dataset)
#define NN 20000
#define EE 320000
#define DD 256

// ---- device scratch (no allocs allowed) ----
__device__ int   g_cnt[2][NN];       // per-row edge counts
__device__ int   g_cur[2][NN];       // scatter cursors
__device__ int   g_rp [2][NN + 1];   // CSR row pointers
__device__ int   g_cols[2][EE];      // permuted col indices
__device__ float g_vals[2][EE];      // permuted edge values

// ---- 1) zero counters/cursors ----
__global__ void k_zero(int n) {
    int i = blockIdx.x * blockDim.x + threadIdx.x;
    if (i < n) {
        g_cnt[0][i] = 0; g_cnt[1][i] = 0;
        g_cur[0][i] = 0; g_cur[1][i] = 0;
    }
}

// ---- 2) histogram of rows for both adjacencies ----
__global__ void k_hist(const int* __restrict__ r1, const int* __restrict__ r2, int E) {
    int i = blockIdx.x * blockDim.x + threadIdx.x;
    if (i < E) {
        atomicAdd(&g_cnt[0][r1[i]], 1);
    } else if (i < 2 * E) {
        atomicAdd(&g_cnt[1][r2[i - E]], 1);
    }
}

// ---- 3) single-block exclusive scan (n <= 20480) ----
__global__ void k_scan(int n) {
    const int IPT = 20;                   // 1024 * 20 = 20480 >= NN
    __shared__ int wsum[32];
    int t = threadIdx.x, lane = t & 31, w = t >> 5;
    for (int a = 0; a < 2; a++) {
        const int* cnt = g_cnt[a];
        int* rp = g_rp[a];
        int base = t * IPT;
        int local[IPT];
        int sum = 0;
#pragma unroll
        for (int i = 0; i < IPT; i++) {
            int idx = base + i;
            int v = (idx < n) ? cnt[idx] : 0;
            local[i] = v;
            sum += v;
        }
        // warp inclusive scan of per-thread sums
        int incl = sum;
#pragma unroll
        for (int off = 1; off < 32; off <<= 1) {
            int u = __shfl_up_sync(0xffffffffu, incl, off);
            if (lane >= off) incl += u;
        }
        if (lane == 31) wsum[w] = incl;
        __syncthreads();
        if (w == 0) {
            int v = wsum[lane];
            int wi = v;
#pragma unroll
            for (int off = 1; off < 32; off <<= 1) {
                int u = __shfl_up_sync(0xffffffffu, wi, off);
                if (lane >= off) wi += u;
            }
            wsum[lane] = wi - v;          // exclusive warp offsets
        }
        __syncthreads();
        int run = wsum[w] + incl - sum;   // exclusive prefix at this thread's first element
#pragma unroll
        for (int i = 0; i < IPT; i++) {
            int idx = base + i;
            if (idx < n) rp[idx] = run;
            run += local[i];
        }
        if (t == 1023) rp[n] = run;       // == E
        __syncthreads();
    }
}

// ---- 4) scatter edges into CSR order ----
__global__ void k_scatter(const int* __restrict__ row, const int* __restrict__ col,
                          const float* __restrict__ val, int E, int a) {
    int i = blockIdx.x * blockDim.x + threadIdx.x;
    if (i >= E) return;
    int r = row[i];
    int p = g_rp[a][r] + atomicAdd(&g_cur[a][r], 1);
    g_cols[a][p] = col[i];
    g_vals[a][p] = val[i];
}

// ---- 5) SpMM: one warp per (row, adjacency); 8 fp32 acc/lane covers D=256 ----
__global__ void __launch_bounds__(256) k_spmm(const float* __restrict__ x,
                                              float* __restrict__ out, int n) {
    int gw = (blockIdx.x * blockDim.x + threadIdx.x) >> 5;
    int lane = threadIdx.x & 31;
    if (gw >= 2 * n) return;
    int a = (gw >= n) ? 1 : 0;
    int r = gw - a * n;
    int s = g_rp[a][r];
    int e = g_rp[a][r + 1];
    const int*   cols = g_cols[a];
    const float* vals = g_vals[a];

    float4 acc0 = make_float4(0.f, 0.f, 0.f, 0.f);
    float4 acc1 = make_float4(0.f, 0.f, 0.f, 0.f);

    for (int k = s; k < e; k++) {
        int   c = __ldg(&cols[k]);
        float v = __ldg(&vals[k]);
        const float4* xr = (const float4*)(x + (size_t)c * DD);
        float4 b0 = __ldg(&xr[lane]);
        float4 b1 = __ldg(&xr[lane + 32]);
        acc0.x += v * b0.x; acc0.y += v * b0.y;
        acc0.z += v * b0.z; acc0.w += v * b0.w;
        acc1.x += v * b1.x; acc1.y += v * b1.y;
        acc1.z += v * b1.z; acc1.w += v * b1.w;
    }

    float4* o = (float4*)(out + (size_t)r * (2 * DD) + (size_t)a * DD);
    o[lane]      = acc0;
    o[lane + 32] = acc1;
}

extern "C" void kernel_launch(void* const* d_in, const int* in_sizes, int n_in,
                              void* d_out, int out_size) {
    const float* x    = (const float*)d_in[0];
    const int*   row1 = (const int*)  d_in[1];
    const int*   col1 = (const int*)  d_in[2];
    const float* val1 = (const float*)d_in[3];
    const int*   row2 = (const int*)  d_in[4];
    const int*   col2 = (const int*)  d_in[5];
    const float* val2 = (const float*)d_in[6];
    float* out = (float*)d_out;

    int n = in_sizes[0] / DD;   // 20000
    int E = in_sizes[1];        // 320000

    // 1) zero counters + cursors
    k_zero<<<(n + 255) / 256, 256>>>(n);
    // 2) histogram both adjacencies
    k_hist<<<(2 * E + 255) / 256, 256>>>(row1, row2, E);
    // 3) row-ptr scan (single block)
    k_scan<<<1, 1024>>>(n);
    // 4) scatter into CSR order
    k_scatter<<<(E + 255) / 256, 256>>>(row1, col1, val1, E, 0);
    k_scatter<<<(E + 255) / 256, 256>>>(row2, col2, val2, E, 1);
    // 5) SpMM, one warp per (row, adjacency)
    int warps = 2 * n;
    int blocks = (warps * 32 + 255) / 256;
    k_spmm<<<blocks, 256>>>(x, out, n);
}